// round 16
// baseline (speedup 1.0000x reference)
#include <cuda_runtime.h>
#include <cuda_fp16.h>
#include <math.h>
#include <float.h>
#include <stdint.h>

// Problem dims
#define BBs   128
#define Ls    343
#define Es    256
#define Hs    8
#define HDs   32
#define HIDs  512
#define LLs   (Ls * Ls)       // 117649
#define ROWSs (BBs * Ls)      // 43904
#define NCLS  2197
#define MW    12
#define MROWS 352             // padded rows for bias/mask tables
#define BSTR  384             // padded cols for bias table
#define MASKG ((BBs * MROWS * MW + 255) / 256)   // 2112

// -------- scratch (device globals; no allocation allowed) --------
__device__ float g_bias[Hs * MROWS * BSTR];     // pad region may be garbage (masked)
__device__ __align__(16) float g_blut[NCLS * 8];
__device__ uint32_t g_maskb[BBs * MROWS * MW];  // pad rows/cols hard-masked
__device__ __half g_xq[ROWSs * Es], g_xk[ROWSs * Es], g_xv[ROWSs * Es];
__device__ __half g_a[ROWSs * Es];
__device__ __half g_w4[4 * Es * Es];
__device__ __half g_qh[BBs * Hs * Ls * HDs];
__device__ __half g_kh[BBs * Hs * Ls * HDs];
__device__ __half g_vh[BBs * Hs * Ls * HDs];

// ============================================================
// PTX helpers
// ============================================================
__device__ __forceinline__ uint32_t smem_u32(const void* p) {
    uint32_t a;
    asm("{ .reg .u64 t; cvta.to.shared.u64 t, %1; cvt.u32.u64 %0, t; }" : "=r"(a) : "l"(p));
    return a;
}
__device__ __forceinline__ void ldsm_x4(uint32_t& r0, uint32_t& r1, uint32_t& r2,
                                        uint32_t& r3, uint32_t addr) {
    asm volatile("ldmatrix.sync.aligned.m8n8.x4.shared.b16 {%0,%1,%2,%3}, [%4];"
                 : "=r"(r0), "=r"(r1), "=r"(r2), "=r"(r3) : "r"(addr));
}
__device__ __forceinline__ void ldsm_x4_t(uint32_t& r0, uint32_t& r1, uint32_t& r2,
                                          uint32_t& r3, uint32_t addr) {
    asm volatile("ldmatrix.sync.aligned.m8n8.x4.trans.shared.b16 {%0,%1,%2,%3}, [%4];"
                 : "=r"(r0), "=r"(r1), "=r"(r2), "=r"(r3) : "r"(addr));
}
__device__ __forceinline__ void mma16816(float* c, const uint32_t* a,
                                         uint32_t b0, uint32_t b1) {
    asm volatile(
        "mma.sync.aligned.m16n8k16.row.col.f32.f16.f16.f32 "
        "{%0,%1,%2,%3}, {%4,%5,%6,%7}, {%8,%9}, {%0,%1,%2,%3};"
        : "+f"(c[0]), "+f"(c[1]), "+f"(c[2]), "+f"(c[3])
        : "r"(a[0]), "r"(a[1]), "r"(a[2]), "r"(a[3]), "r"(b0), "r"(b1));
}
__device__ __forceinline__ void cp_async16(uint32_t dst, const void* src) {
    asm volatile("cp.async.cg.shared.global [%0], [%1], 16;" :: "r"(dst), "l"(src));
}
__device__ __forceinline__ void cp_commit() { asm volatile("cp.async.commit_group;"); }
__device__ __forceinline__ void cp_wait1() { asm volatile("cp.async.wait_group 1;"); }
__device__ __forceinline__ void cp_wait0() { asm volatile("cp.async.wait_group 0;"); }

__device__ __forceinline__ uint32_t packh(float a, float b) {
    __half2 t = __floats2half2_rn(a, b);
    return *(uint32_t*)&t;
}

// Fast exp on FMA/ALU pipes only (no MUFU). rel err ~2.4e-6.
__device__ __forceinline__ float fexp(float x) {
    float y = fmaxf(x * 1.4426950408889634f, -126.0f);
    float yr = __fadd_rn(y, 12582912.0f);
    float n  = __fsub_rn(yr, 12582912.0f);
    float f  = __fsub_rn(y, n);
    float p  = 1.3333558e-3f;
    p = fmaf(p, f, 9.6181291e-3f);
    p = fmaf(p, f, 5.5504109e-2f);
    p = fmaf(p, f, 2.4022651e-1f);
    p = fmaf(p, f, 6.9314718e-1f);
    p = fmaf(p, f, 1.0f);
    return __int_as_float(__float_as_int(p) + (__float_as_int(yr) << 23));
}

// ============================================================
// Launch 1: inputs->fp16 (y=0..2) + weight transpose->fp16 (y=3)
// ============================================================
__global__ __launch_bounds__(256) void prep_kernel(
    const float4* __restrict__ q, const float4* __restrict__ k,
    const float4* __restrict__ v, int n4,
    const float* __restrict__ Wq, const float* __restrict__ Wk,
    const float* __restrict__ Wv, const float* __restrict__ Ww)
{
    __shared__ float t[32][33];
    if (blockIdx.y < 3) {
        const int z = blockIdx.y;
        const float4* in = (z == 0) ? q : (z == 1) ? k : v;
        __half* dst = (z == 0) ? g_xq : (z == 1) ? g_xk : g_xv;
        int i = blockIdx.x * 256 + threadIdx.x;
        if (i >= n4) return;
        float4 val = in[i];
        uint2 o = make_uint2(packh(val.x, val.y), packh(val.z, val.w));
        *(uint2*)(dst + (size_t)i * 4) = o;
    } else {
        if (blockIdx.x >= 256) return;
        int b = blockIdx.x;
        int z = b >> 6, rem = b & 63;
        int bn = (rem & 7) * 32, bk = (rem >> 3) * 32;
        const float* W = (z == 0) ? Wq : (z == 1) ? Wk : (z == 2) ? Wv : Ww;
        __half* ht = g_w4 + (size_t)z * Es * Es;
        int lx = threadIdx.x & 31, ly = threadIdx.x >> 5;
        for (int yy = ly; yy < 32; yy += 8)
            t[yy][lx] = W[(size_t)(bk + yy) * Es + bn + lx];
        __syncthreads();
        for (int yy = ly; yy < 32; yy += 8)
            ht[(size_t)(bn + yy) * Es + bk + lx] = __float2half_rn(t[lx][yy]);
    }
}

// ============================================================
// Launch 2: mask bit-pack (pad rows/cols hard-masked) + CPB LUT
// ============================================================
__global__ __launch_bounds__(256) void mask_lut_kernel(
    const void* __restrict__ maskp,
    const float* __restrict__ W1, const float* __restrict__ b1,
    const float* __restrict__ W2, const float* __restrict__ b2)
{
    if (blockIdx.x < MASKG) {
        __shared__ int s_float, s_multi;
        if (threadIdx.x == 0) { s_float = 0; s_multi = 0; }
        __syncthreads();
        const unsigned int* m = (const unsigned int*)maskp;
        for (int i = threadIdx.x; i < 4096; i += 256) {
            unsigned int w = m[i];
            if (w == 0x3F800000u) atomicOr(&s_float, 1);
            else if (w != 0u && (w & 0xFFFFFF00u) != 0u) atomicOr(&s_multi, 1);
        }
        __syncthreads();
        const int mode = s_float ? 2 : (s_multi ? 0 : 1);

        int idx = blockIdx.x * 256 + threadIdx.x;
        if (idx >= BBs * MROWS * MW) return;
        int w = idx % MW;
        int tt = idx / MW;
        int row = tt % MROWS;
        int bb = tt / MROWS;
        uint32_t bits;
        if (row >= Ls) {
            bits = 0xFFFFFFFFu;                         // pad rows fully masked
        } else {
            const size_t rbase = (size_t)bb * LLs + (size_t)row * Ls;
            int c0 = w * 32;
            int cend = Ls - c0;                          // may be <=0
            if (cend <= 0) {
                bits = 0xFFFFFFFFu;                      // pad cols fully masked
            } else {
                if (cend > 32) cend = 32;
                bits = (cend < 32) ? ~((1u << cend) - 1u) : 0u;  // mask col pads
                if (mode == 0) {
                    const uint8_t* p = (const uint8_t*)maskp + rbase + c0;
                    for (int b = 0; b < cend; b++) if (p[b]) bits |= (1u << b);
                } else if (mode == 1) {
                    const int* p = (const int*)maskp + rbase + c0;
                    for (int b = 0; b < cend; b++) if (p[b]) bits |= (1u << b);
                } else {
                    const float* p = (const float*)maskp + rbase + c0;
                    for (int b = 0; b < cend; b++) if (p[b] != 0.0f) bits |= (1u << b);
                }
            }
        }
        g_maskb[((size_t)bb * MROWS + row) * MW + w] = bits;
    } else {
        int wid = threadIdx.x >> 5, lane = threadIdx.x & 31;
        int cls = (blockIdx.x - MASKG) * 8 + wid;
        if (cls >= NCLS) return;
        int d0 = cls % 13 - 6;
        int d1 = (cls / 13) % 13 - 6;
        int d2 = cls / 169 - 6;
        float x0 = copysignf(log2f(1.0f + fabsf((float)d0)) * (1.0f / 3.0f), (float)d0);
        float x1 = copysignf(log2f(1.0f + fabsf((float)d1)) * (1.0f / 3.0f), (float)d1);
        float x2 = copysignf(log2f(1.0f + fabsf((float)d2)) * (1.0f / 3.0f), (float)d2);
        float acc[8];
#pragma unroll
        for (int h = 0; h < 8; h++) acc[h] = 0.0f;
        for (int t = lane; t < HIDs; t += 32) {
            float hv = fmaxf(fmaf(x0, W1[t], fmaf(x1, W1[HIDs + t],
                            fmaf(x2, W1[2 * HIDs + t], b1[t]))), 0.0f);
#pragma unroll
            for (int h = 0; h < 8; h++) acc[h] = fmaf(hv, W2[t * 8 + h], acc[h]);
        }
#pragma unroll
        for (int h = 0; h < 8; h++) {
#pragma unroll
            for (int o = 16; o > 0; o >>= 1)
                acc[h] += __shfl_xor_sync(0xffffffffu, acc[h], o);
        }
        if (lane == 0) {
#pragma unroll
            for (int h = 0; h < 8; h++) {
                float z = acc[h] + b2[h];
                g_blut[cls * 8 + h] = 16.0f / (1.0f + fexp(-z));
            }
        }
    }
}

// ============================================================
// Shared fp16 GEMM body
// ============================================================
#define TGS 72
#define TGBUF 18432
#define TGSTAGE (2 * TGBUF)
#define TG_SMEM (3 * TGSTAGE)

__device__ __forceinline__ void tgemm_body(
    char* dsm,
    const __half* __restrict__ A, const __half* __restrict__ W,
    const float* __restrict__ bias, float* __restrict__ C, int remap,
    __half* __restrict__ Oh, int donorm)
{
    const int tid = threadIdx.x;
    const int wid = tid >> 5;
    const int lane = tid & 31;
    const int m0 = blockIdx.x * 128;
    const int n0 = blockIdx.y * 128;
    const int wm = wid & 1;
    const int wn = wid >> 1;
    const uint32_t smb = smem_u32(dsm);

    float c[4][4][4];
#pragma unroll
    for (int i = 0; i < 4; i++)
#pragma unroll
        for (int j = 0; j < 4; j++)
#pragma unroll
            for (int k = 0; k < 4; k++) c[i][j][k] = 0.0f;

    auto prefetch = [&](int i) {
        const int s = i % 3;
        const int k0 = i * 64;
        const uint32_t bA = smb + s * TGSTAGE;
        const uint32_t bB = bA + TGBUF;
#pragma unroll
        for (int j = 0; j < 4; j++) {
            int x = tid + j * 256;
            int r = x >> 3, cc = x & 7;
            uint32_t off = (uint32_t)(r * TGS + cc * 8) * 2;
            cp_async16(bA + off, A + (size_t)(m0 + r) * Es + k0 + cc * 8);
            cp_async16(bB + off, W + (size_t)(n0 + r) * Es + k0 + cc * 8);
        }
    };

    prefetch(0); cp_commit();
    prefetch(1); cp_commit();

    const int arow = (lane & 7) + ((lane >> 3) & 1) * 8;
    const int acolo = ((lane >> 4) & 1) * 8;
    const int brow = (lane & 7) + ((lane >> 4) & 1) * 8;
    const int bcolo = ((lane >> 3) & 1) * 8;

    for (int i = 0; i < 4; i++) {
        if (i < 3) cp_wait1(); else cp_wait0();
        __syncthreads();
        if (i < 2) { prefetch(i + 2); cp_commit(); }

        const uint32_t bA = smb + (i % 3) * TGSTAGE;
        const uint32_t bB = bA + TGBUF;
#pragma unroll
        for (int ks = 0; ks < 4; ks++) {
            const int k0 = ks * 16;
            uint32_t a[4][4], b[2][4];
#pragma unroll
            for (int mt = 0; mt < 4; mt++)
                ldsm_x4(a[mt][0], a[mt][1], a[mt][2], a[mt][3],
                        bA + (uint32_t)((wm * 64 + mt * 16 + arow) * TGS + k0 + acolo) * 2);
#pragma unroll
            for (int g = 0; g < 2; g++)
                ldsm_x4(b[g][0], b[g][1], b[g][2], b[g][3],
                        bB + (uint32_t)((wn * 32 + g * 16 + brow) * TGS + k0 + bcolo) * 2);
#pragma unroll
            for (int mt = 0; mt < 4; mt++)
#pragma unroll
                for (int nt = 0; nt < 4; nt++)
                    mma16816(c[mt][nt], a[mt], b[nt >> 1][(nt & 1) * 2],
                             b[nt >> 1][(nt & 1) * 2 + 1]);
        }
    }

    const int tq = lane >> 2;
    const int tr = lane & 3;
#pragma unroll
    for (int mt = 0; mt < 4; mt++) {
        const int m = m0 + wm * 64 + mt * 16 + tq;
        float v0x[4], v0y[4], v1x[4], v1y[4];
#pragma unroll
        for (int nt = 0; nt < 4; nt++) {
            const int n = n0 + wn * 32 + nt * 8 + tr * 2;
            float bx = 0.0f, by = 0.0f;
            if (bias) { float2 bv = *(const float2*)(bias + n); bx = bv.x; by = bv.y; }
            v0x[nt] = c[mt][nt][0] + bx; v0y[nt] = c[mt][nt][1] + by;
            v1x[nt] = c[mt][nt][2] + bx; v1y[nt] = c[mt][nt][3] + by;
        }
        if (donorm) {
            float ss0 = 0.0f, ss1 = 0.0f;
#pragma unroll
            for (int nt = 0; nt < 4; nt++) {
                ss0 = fmaf(v0x[nt], v0x[nt], fmaf(v0y[nt], v0y[nt], ss0));
                ss1 = fmaf(v1x[nt], v1x[nt], fmaf(v1y[nt], v1y[nt], ss1));
            }
            ss0 += __shfl_xor_sync(0xffffffffu, ss0, 1);
            ss0 += __shfl_xor_sync(0xffffffffu, ss0, 2);
            ss1 += __shfl_xor_sync(0xffffffffu, ss1, 1);
            ss1 += __shfl_xor_sync(0xffffffffu, ss1, 2);
            float i0 = 1.0f / fmaxf(sqrtf(ss0), 1e-12f);
            float i1 = 1.0f / fmaxf(sqrtf(ss1), 1e-12f);
#pragma unroll
            for (int nt = 0; nt < 4; nt++) {
                v0x[nt] *= i0; v0y[nt] *= i0;
                v1x[nt] *= i1; v1y[nt] *= i1;
            }
        }
#pragma unroll
        for (int nt = 0; nt < 4; nt++) {
            const int n = n0 + wn * 32 + nt * 8 + tr * 2;
            size_t a0, a1;
            if (remap) {
                const int hh = n >> 5, hd = n & 31;
                int bbw = m / Ls, l = m - bbw * Ls;
                a0 = ((size_t)(bbw * Hs + hh) * Ls + l) * HDs + hd;
                int m2 = m + 8;
                int bbw2 = m2 / Ls, l2 = m2 - bbw2 * Ls;
                a1 = ((size_t)(bbw2 * Hs + hh) * Ls + l2) * HDs + hd;
            } else {
                a0 = (size_t)m * Es + n;
                a1 = (size_t)(m + 8) * Es + n;
            }
            if (Oh) {
                *(uint32_t*)(Oh + a0) = packh(v0x[nt], v0y[nt]);
                *(uint32_t*)(Oh + a1) = packh(v1x[nt], v1y[nt]);
            } else {
                *(float2*)(C + a0) = make_float2(v0x[nt], v0y[nt]);
                *(float2*)(C + a1) = make_float2(v1x[nt], v1y[nt]);
            }
        }
    }
}

// Launch 3: Q/K/V projections (z=0..2) + bias gather (z=3)
__global__ __launch_bounds__(256, 2) void qkv_gemm_kernel(
    const float* __restrict__ bq, const float* __restrict__ bk,
    const float* __restrict__ indices)
{
    extern __shared__ char dsm[];
    const int z = blockIdx.z;
    if (z == 3) {
        int p = (blockIdx.y * gridDim.x + blockIdx.x) * 256 + threadIdx.x;
        if (p >= LLs) return;
        int i = p / Ls, j = p - i * Ls;
        int q0 = __float2int_rn(indices[p * 3 + 0]) + 6;
        int q1 = __float2int_rn(indices[p * 3 + 1]) + 6;
        int q2 = __float2int_rn(indices[p * 3 + 2]) + 6;
        int cls = q0 + 13 * q1 + 169 * q2;
        float4 v0 = *(const float4*)(g_blut + cls * 8);
        float4 v1 = *(const float4*)(g_blut + cls * 8 + 4);
        float vals[8] = { v0.x, v0.y, v0.z, v0.w, v1.x, v1.y, v1.z, v1.w };
#pragma unroll
        for (int h = 0; h < 8; h++)
            g_bias[(size_t)h * (MROWS * BSTR) + i * BSTR + j] = vals[h];
        return;
    }
    const __half* A  = (z == 0) ? g_xq : (z == 1) ? g_xk : g_xv;
    const __half* W  = g_w4 + (size_t)z * Es * Es;
    const float* bias = (z == 0) ? bq : (z == 1) ? bk : nullptr;
    __half* Oh = (z == 0) ? g_qh : (z == 1) ? g_kh : g_vh;
    tgemm_body(dsm, A, W, bias, nullptr, 1, Oh, z < 2);
}

// Launch 5: output projection -> fp32 d_out
__global__ __launch_bounds__(256, 2) void out_gemm_kernel(
    const float* __restrict__ bw, float* __restrict__ out)
{
    extern __shared__ char dsm[];
    tgemm_body(dsm, g_a, g_w4 + 3 * (size_t)Es * Es, bw, out, 0, nullptr, 0);
}

// ============================================================
// Launch 4: persistent fp16 attention per (head, window).
// 256 threads / 8 warps; 110.6 KB SMEM -> 2 CTAs/SM.
// Padded tables -> NO per-element bounds predication.
// ============================================================
#define ASTR 40
#define ABUF 30720
#define OFF_QH (0 * ABUF)
#define OFF_KH (1 * ABUF)
#define OFF_VH (2 * ABUF)
#define OFF_RMAX (3 * ABUF)
#define OFF_RSUM (OFF_RMAX + 512)
#define OFF_ORED (OFF_RSUM + 512)
#define ORSTR 34
#define ATT3_SMEM (OFF_ORED + 4 * 32 * ORSTR * 4)   // 110592

__global__ __launch_bounds__(256, 2) void attn3_kernel(const float* __restrict__ scalep)
{
    extern __shared__ char sm2[];
    float* redmax = (float*)(sm2 + OFF_RMAX);
    float* redsum = (float*)(sm2 + OFF_RSUM);
    float* ored   = (float*)(sm2 + OFF_ORED);
    const uint32_t smb = smem_u32(sm2);

    const int tid = threadIdx.x;
    const int wid = tid >> 5;
    const int lane = tid & 31;
    const int h = blockIdx.x;
    const int bb = blockIdx.y;
    const size_t gbase = (size_t)(bb * Hs + h) * (Ls * HDs);

    // ---- fill Q,K,V once ----
    {
        const __half* gsrc[3] = { g_qh + gbase, g_kh + gbase, g_vh + gbase };
#pragma unroll
        for (int arr = 0; arr < 3; arr++)
            for (int i = tid; i < 1372; i += 256) {
                int row = i >> 2, ch = i & 3;
                cp_async16(smb + arr * ABUF + row * 80 + ch * 16,
                           gsrc[arr] + row * HDs + ch * 8);
            }
        for (int i = tid; i < 492; i += 256) {
            int arr = i / 164, j = i - arr * 164;
            int r = 343 + (j >> 2), ch = j & 3;
            *(uint4*)(sm2 + arr * ABUF + r * 80 + ch * 16) = make_uint4(0, 0, 0, 0);
        }
        cp_commit();
        cp_wait0();
        __syncthreads();
    }

    const int wm = wid & 1;
    const int wn = wid >> 1;
    const int nbase = wn * 96;

    const int arow = (lane & 7) + ((lane >> 3) & 1) * 8;
    const int acolo = ((lane >> 4) & 1) * 8;
    const int brow = (lane & 7) + ((lane >> 4) & 1) * 8;
    const int bcolo = ((lane >> 3) & 1) * 8;

    const float invscale = 1.0f / fmaxf(scalep[0], 0.01f);
    const float* bias0 = g_bias + (size_t)h * (MROWS * BSTR);
    const uint32_t* mrowb = g_maskb + (size_t)bb * (MROWS * MW) + wn * 3;
    const int r0 = wm * 16 + (lane >> 2);
    const int r1 = r0 + 8;
    const int ncol = (lane & 3) * 2;
    const int lane16 = lane & 15;
    const int halfr = lane >> 4;

    for (int qt = 0; qt < 11; qt++) {
        const int q0 = qt * 32;
        const int qrow0 = q0 + r0, qrow1 = q0 + r1;

        // ---- mask words (unconditional; tables are padded) ----
        const uint32_t* mp0 = mrowb + (size_t)qrow0 * MW;
        const uint32_t* mp1 = mrowb + (size_t)qrow1 * MW;
        uint32_t mw0[3] = { mp0[0], mp0[1], mp0[2] };
        uint32_t mw1[3] = { mp1[0], mp1[1], mp1[2] };
        const float* brow0 = bias0 + (size_t)qrow0 * BSTR + nbase + ncol;
        const float* brow1 = bias0 + (size_t)qrow1 * BSTR + nbase + ncol;

        // ---- Q fragments ----
        uint32_t qh[2][4];
#pragma unroll
        for (int kk = 0; kk < 2; kk++) {
            uint32_t ro = (uint32_t)((q0 + wm * 16 + arow) * ASTR + kk * 16 + acolo) * 2;
            ldsm_x4(qh[kk][0], qh[kk][1], qh[kk][2], qh[kk][3], smb + OFF_QH + ro);
        }

        // ---- fused phase 1 (no bounds predication) ----
        float c[12][4];
        float mx0 = -FLT_MAX, mx1 = -FLT_MAX;
#pragma unroll
        for (int g = 0; g < 6; g++) {
            float2 bT00 = *(const float2*)(brow0 + g * 16);
            float2 bT10 = *(const float2*)(brow0 + g * 16 + 8);
            float2 bT01 = *(const float2*)(brow1 + g * 16);
            float2 bT11 = *(const float2*)(brow1 + g * 16 + 8);

            uint32_t bh[2][4];
#pragma unroll
            for (int kk = 0; kk < 2; kk++) {
                uint32_t rb = (uint32_t)((nbase + g * 16 + brow) * ASTR + kk * 16 + bcolo) * 2;
                ldsm_x4(bh[kk][0], bh[kk][1], bh[kk][2], bh[kk][3], smb + OFF_KH + rb);
            }
            float cg[2][4];
#pragma unroll
            for (int nt = 0; nt < 2; nt++)
#pragma unroll
                for (int e = 0; e < 4; e++) cg[nt][e] = 0.0f;
#pragma unroll
            for (int kk = 0; kk < 2; kk++)
#pragma unroll
                for (int nt = 0; nt < 2; nt++)
                    mma16816(cg[nt], qh[kk], bh[kk][nt * 2], bh[kk][nt * 2 + 1]);
#pragma unroll
            for (int nt = 0; nt < 2; nt++) {
                const int t = g * 2 + nt;
                const int base = g * 16 + nt * 8;
                const int wI = base >> 5;
                uint32_t mb0 = (mw0[wI] >> ((base & 31) + ncol)) & 3u;
                uint32_t mb1 = (mw1[wI] >> ((base & 31) + ncol)) & 3u;
                float2 b0v = nt ? bT10 : bT00;
                float2 b1v = nt ? bT11 : bT01;
                c[t][0] = (mb0 & 1u) ? -100000.0f : fmaf(cg[nt][0], invscale, b0v.x);
                c[t][1] = (mb0 & 2u) ? -100000.0f : fmaf(cg[nt][1], invscale, b0v.y);
                c[t][2] = (mb1 & 1u) ? -100000.0f : fmaf(cg[nt][2], invscale, b1v.x);
                c[t][3] = (mb1 & 2u) ? -100000.0f : fmaf(cg[nt][3], invscale, b1v.y);
                mx0 = fmaxf(mx0, fmaxf(c[t][0], c[t][1]));
                mx1 = fmaxf(mx1, fmaxf(c[t][2], c[t][3]));
            }
        }

        // ---- single-sync softmax; normalization deferred to post-PV ----
        mx0 = fmaxf(mx0, __shfl_xor_sync(0xffffffffu, mx0, 1));
        mx0 = fmaxf(mx0, __shfl_xor_sync(0xffffffffu, mx0, 2));
        mx1 = fmaxf(mx1, __shfl_xor_sync(0xffffffffu, mx1, 1));
        mx1 = fmaxf(mx1, __shfl_xor_sync(0xffffffffu, mx1, 2));

        float s0 = 0.0f, s1 = 0.0f;
#pragma unroll
        for (int t = 0; t < 12; t++) {
            float e0 = fexp(c[t][0] - mx0); c[t][0] = e0; s0 += e0;
            float e1 = fexp(c[t][1] - mx0); c[t][1] = e1; s0 += e1;
            float e2 = fexp(c[t][2] - mx1); c[t][2] = e2; s1 += e2;
            float e3 = fexp(c[t][3] - mx1); c[t][3] = e3; s1 += e3;
        }
        s0 += __shfl_xor_sync(0xffffffffu, s0, 1);
        s0 += __shfl_xor_sync(0xffffffffu, s0, 2);
        s1 += __shfl_xor_sync(0xffffffffu, s1, 1);
        s1 += __shfl_xor_sync(0xffffffffu, s1, 2);
        if ((lane & 3) == 0) {
            redmax[wn * 32 + r0] = mx0; redsum[wn * 32 + r0] = s0;
            redmax[wn * 32 + r1] = mx1; redsum[wn * 32 + r1] = s1;
        }
        __syncthreads();
        float f0, f1;
        {
            float gm0 = -FLT_MAX, gm1 = -FLT_MAX;
#pragma unroll
            for (int qd = 0; qd < 4; qd++) {
                gm0 = fmaxf(gm0, redmax[qd * 32 + r0]);
                gm1 = fmaxf(gm1, redmax[qd * 32 + r1]);
            }
            float S0 = 0.0f, S1 = 0.0f;
#pragma unroll
            for (int qd = 0; qd < 4; qd++) {
                S0 += redsum[qd * 32 + r0] * fexp(redmax[qd * 32 + r0] - gm0);
                S1 += redsum[qd * 32 + r1] * fexp(redmax[qd * 32 + r1] - gm1);
            }
            f0 = fexp(mx0 - gm0) / S0;
            f1 = fexp(mx1 - gm1) / S1;
        }

        // ---- phase 3: O = P * V, then scale by f ----
        float oc[4][4];
#pragma unroll
        for (int nt = 0; nt < 4; nt++)
#pragma unroll
            for (int e = 0; e < 4; e++) oc[nt][e] = 0.0f;

#pragma unroll
        for (int kt = 0; kt < 6; kt++) {
            uint32_t ph[4];
#pragma unroll
            for (int half = 0; half < 2; half++) {
                const float* cc = c[2 * kt + half];
                ph[half * 2 + 0] = packh(cc[0], cc[1]);
                ph[half * 2 + 1] = packh(cc[2], cc[3]);
            }
            const int krow = nbase + kt * 16;
            uint32_t vh[2][4];
#pragma unroll
            for (int g = 0; g < 2; g++) {
                uint32_t ad = (uint32_t)((krow + arow) * ASTR + g * 16 + acolo) * 2;
                ldsm_x4_t(vh[g][0], vh[g][1], vh[g][2], vh[g][3], smb + OFF_VH + ad);
            }
#pragma unroll
            for (int nt = 0; nt < 4; nt++) {
                const int g = nt >> 1, i2 = (nt & 1) * 2;
                mma16816(oc[nt], ph, vh[g][i2], vh[g][i2 + 1]);
            }
        }
#pragma unroll
        for (int nt = 0; nt < 4; nt++) {
            oc[nt][0] *= f0; oc[nt][1] *= f0;
            oc[nt][2] *= f1; oc[nt][3] *= f1;
        }

        // ---- 4 slabs + distributed reduce + fp16 store ----
        {
            float* dst = ored + (size_t)wn * (32 * ORSTR);
#pragma unroll
            for (int nt = 0; nt < 4; nt++) {
                *(float2*)(dst + r0 * ORSTR + nt * 8 + ncol) = make_float2(oc[nt][0], oc[nt][1]);
                *(float2*)(dst + r1 * ORSTR + nt * 8 + ncol) = make_float2(oc[nt][2], oc[nt][3]);
            }
        }
        __syncthreads();
#pragma unroll
        for (int p = 0; p < 2; p++) {
            int row = wid * 4 + p * 2 + halfr;
            int qrow = q0 + row;
            if (qrow < Ls) {
                int col = lane16 * 2;
                float s0o = 0.0f, s1o = 0.0f;
#pragma unroll
                for (int qd = 0; qd < 4; qd++) {
                    float2 v = *(float2*)(ored + qd * (32 * ORSTR) + row * ORSTR + col);
                    s0o += v.x; s1o += v.y;
                }
                size_t ad = (size_t)(bb * Ls + qrow) * Es + h * HDs + col;
                *(uint32_t*)(g_a + ad) = packh(s0o, s1o);
            }
        }
        __syncthreads();
    }
}

// ============================================================
// launch
// ============================================================
extern "C" void kernel_launch(void* const* d_in, const int* in_sizes, int n_in,
                              void* d_out, int out_size)
{
    (void)in_sizes; (void)n_in; (void)out_size;
    const float* query   = (const float*)d_in[0];
    const float* key     = (const float*)d_in[1];
    const float* value   = (const float*)d_in[2];
    const float* indices = (const float*)d_in[3];
    const void*  mask    = d_in[4];
    const float* Wq      = (const float*)d_in[5];
    const float* bq      = (const float*)d_in[6];
    const float* Wk      = (const float*)d_in[7];
    const float* bk      = (const float*)d_in[8];
    const float* Wv      = (const float*)d_in[9];
    const float* Ww      = (const float*)d_in[10];
    const float* bw      = (const float*)d_in[11];
    const float* scale   = (const float*)d_in[12];
    const float* W1      = (const float*)d_in[13];
    const float* b1      = (const float*)d_in[14];
    const float* W2      = (const float*)d_in[15];
    const float* b2      = (const float*)d_in[16];
    float* out = (float*)d_out;

    cudaFuncSetAttribute(qkv_gemm_kernel, cudaFuncAttributeMaxDynamicSharedMemorySize,
                         TG_SMEM);
    cudaFuncSetAttribute(out_gemm_kernel, cudaFuncAttributeMaxDynamicSharedMemorySize,
                         TG_SMEM);
    cudaFuncSetAttribute(attn3_kernel, cudaFuncAttributeMaxDynamicSharedMemorySize,
                         ATT3_SMEM);

    const int n4 = ROWSs * Es / 4;
    const int splitg = (n4 + 255) / 256;
    const int lutg = (NCLS + 7) / 8;

    prep_kernel<<<dim3(splitg, 4), 256>>>((const float4*)query, (const float4*)key,
                                          (const float4*)value, n4, Wq, Wk, Wv, Ww);
    mask_lut_kernel<<<MASKG + lutg, 256>>>(mask, W1, b1, W2, b2);
    qkv_gemm_kernel<<<dim3(ROWSs / 128, Es / 128, 4), 256, TG_SMEM>>>(bq, bk, indices);
    attn3_kernel<<<dim3(Hs, BBs), 256, ATT3_SMEM>>>(scale);
    out_gemm_kernel<<<dim3(ROWSs / 128, Es / 128), 256, TG_SMEM>>>(bw, out);
}

// round 17
// speedup vs baseline: 1.0039x; 1.0039x over previous
#include <cuda_runtime.h>
#include <cuda_fp16.h>
#include <math.h>
#include <float.h>
#include <stdint.h>

// Problem dims
#define BBs   128
#define Ls    343
#define Es    256
#define Hs    8
#define HDs   32
#define HIDs  512
#define LLs   (Ls * Ls)       // 117649
#define ROWSs (BBs * Ls)      // 43904
#define NCLS  2197
#define MW    12
#define MROWS 352             // padded rows for bias/mask tables
#define BSTR  384             // padded cols for bias table
#define MASKG ((BBs * MROWS * MW + 255) / 256)   // 2112
#define LUTG  ((NCLS + 7) / 8)                   // 275

// -------- scratch (device globals; no allocation allowed) --------
__device__ float g_bias[Hs * MROWS * BSTR];     // pad region 0/garbage (masked)
__device__ __align__(16) float g_blut[NCLS * 8];
__device__ uint32_t g_maskb[BBs * MROWS * MW];  // pad rows/cols hard-masked
__device__ __half g_xq[ROWSs * Es], g_xk[ROWSs * Es], g_xv[ROWSs * Es];
__device__ __half g_a[ROWSs * Es];
__device__ __half g_w4[4 * Es * Es];
__device__ __half g_qh[BBs * Hs * Ls * HDs];
__device__ __half g_kh[BBs * Hs * Ls * HDs];
__device__ __half g_vh[BBs * Hs * Ls * HDs];

// ============================================================
// PTX helpers
// ============================================================
__device__ __forceinline__ uint32_t smem_u32(const void* p) {
    uint32_t a;
    asm("{ .reg .u64 t; cvta.to.shared.u64 t, %1; cvt.u32.u64 %0, t; }" : "=r"(a) : "l"(p));
    return a;
}
__device__ __forceinline__ void ldsm_x4(uint32_t& r0, uint32_t& r1, uint32_t& r2,
                                        uint32_t& r3, uint32_t addr) {
    asm volatile("ldmatrix.sync.aligned.m8n8.x4.shared.b16 {%0,%1,%2,%3}, [%4];"
                 : "=r"(r0), "=r"(r1), "=r"(r2), "=r"(r3) : "r"(addr));
}
__device__ __forceinline__ void ldsm_x4_t(uint32_t& r0, uint32_t& r1, uint32_t& r2,
                                          uint32_t& r3, uint32_t addr) {
    asm volatile("ldmatrix.sync.aligned.m8n8.x4.trans.shared.b16 {%0,%1,%2,%3}, [%4];"
                 : "=r"(r0), "=r"(r1), "=r"(r2), "=r"(r3) : "r"(addr));
}
__device__ __forceinline__ void mma16816(float* c, const uint32_t* a,
                                         uint32_t b0, uint32_t b1) {
    asm volatile(
        "mma.sync.aligned.m16n8k16.row.col.f32.f16.f16.f32 "
        "{%0,%1,%2,%3}, {%4,%5,%6,%7}, {%8,%9}, {%0,%1,%2,%3};"
        : "+f"(c[0]), "+f"(c[1]), "+f"(c[2]), "+f"(c[3])
        : "r"(a[0]), "r"(a[1]), "r"(a[2]), "r"(a[3]), "r"(b0), "r"(b1));
}
__device__ __forceinline__ void cp_async16(uint32_t dst, const void* src) {
    asm volatile("cp.async.cg.shared.global [%0], [%1], 16;" :: "r"(dst), "l"(src));
}
__device__ __forceinline__ void cp_commit() { asm volatile("cp.async.commit_group;"); }
__device__ __forceinline__ void cp_wait1() { asm volatile("cp.async.wait_group 1;"); }
__device__ __forceinline__ void cp_wait0() { asm volatile("cp.async.wait_group 0;"); }

__device__ __forceinline__ uint32_t packh(float a, float b) {
    __half2 t = __floats2half2_rn(a, b);
    return *(uint32_t*)&t;
}

// Fast exp on FMA/ALU pipes only (no MUFU). deg-4 poly, rel err ~4e-5.
__device__ __forceinline__ float fexp(float x) {
    float y = fmaxf(x * 1.4426950408889634f, -126.0f);
    float yr = __fadd_rn(y, 12582912.0f);
    float n  = __fsub_rn(yr, 12582912.0f);
    float f  = __fsub_rn(y, n);
    float p  = 9.6181291e-3f;
    p = fmaf(p, f, 5.5504109e-2f);
    p = fmaf(p, f, 2.4022651e-1f);
    p = fmaf(p, f, 6.9314718e-1f);
    p = fmaf(p, f, 1.0f);
    return __int_as_float(__float_as_int(p) + (__float_as_int(yr) << 23));
}

// ============================================================
// Launch 1: inputs->fp16 (y=0..2) + weights (y=3) + mask pack (y=4)
//           + CPB LUT (y=5)   — all independent work, one launch
// ============================================================
__global__ __launch_bounds__(256) void prep_kernel(
    const float4* __restrict__ q, const float4* __restrict__ k,
    const float4* __restrict__ v, int n4,
    const float* __restrict__ Wq, const float* __restrict__ Wk,
    const float* __restrict__ Wv, const float* __restrict__ Ww,
    const void* __restrict__ maskp,
    const float* __restrict__ W1, const float* __restrict__ b1,
    const float* __restrict__ W2, const float* __restrict__ b2)
{
    __shared__ float t[32][33];
    __shared__ int s_float, s_multi;
    const int y = blockIdx.y;
    if (y < 3) {
        const float4* in = (y == 0) ? q : (y == 1) ? k : v;
        __half* dst = (y == 0) ? g_xq : (y == 1) ? g_xk : g_xv;
        int i = blockIdx.x * 256 + threadIdx.x;
        if (i >= n4) return;
        float4 val = in[i];
        uint2 o = make_uint2(packh(val.x, val.y), packh(val.z, val.w));
        *(uint2*)(dst + (size_t)i * 4) = o;
    } else if (y == 3) {
        if (blockIdx.x >= 256) return;
        int b = blockIdx.x;
        int z = b >> 6, rem = b & 63;
        int bn = (rem & 7) * 32, bk = (rem >> 3) * 32;
        const float* W = (z == 0) ? Wq : (z == 1) ? Wk : (z == 2) ? Wv : Ww;
        __half* ht = g_w4 + (size_t)z * Es * Es;
        int lx = threadIdx.x & 31, ly = threadIdx.x >> 5;
        for (int yy = ly; yy < 32; yy += 8)
            t[yy][lx] = W[(size_t)(bk + yy) * Es + bn + lx];
        __syncthreads();
        for (int yy = ly; yy < 32; yy += 8)
            ht[(size_t)(bn + yy) * Es + bk + lx] = __float2half_rn(t[lx][yy]);
    } else if (y == 4) {
        if (blockIdx.x >= MASKG) return;
        if (threadIdx.x == 0) { s_float = 0; s_multi = 0; }
        __syncthreads();
        const unsigned int* m = (const unsigned int*)maskp;
        for (int i = threadIdx.x; i < 4096; i += 256) {
            unsigned int w = m[i];
            if (w == 0x3F800000u) atomicOr(&s_float, 1);
            else if (w != 0u && (w & 0xFFFFFF00u) != 0u) atomicOr(&s_multi, 1);
        }
        __syncthreads();
        const int mode = s_float ? 2 : (s_multi ? 0 : 1);

        int idx = blockIdx.x * 256 + threadIdx.x;
        if (idx >= BBs * MROWS * MW) return;
        int w = idx % MW;
        int tt = idx / MW;
        int row = tt % MROWS;
        int bb = tt / MROWS;
        uint32_t bits;
        if (row >= Ls) {
            bits = 0xFFFFFFFFu;
        } else {
            const size_t rbase = (size_t)bb * LLs + (size_t)row * Ls;
            int c0 = w * 32;
            int cend = Ls - c0;
            if (cend <= 0) {
                bits = 0xFFFFFFFFu;
            } else {
                if (cend > 32) cend = 32;
                bits = (cend < 32) ? ~((1u << cend) - 1u) : 0u;
                if (mode == 0) {
                    const uint8_t* p = (const uint8_t*)maskp + rbase + c0;
                    for (int b = 0; b < cend; b++) if (p[b]) bits |= (1u << b);
                } else if (mode == 1) {
                    const int* p = (const int*)maskp + rbase + c0;
                    for (int b = 0; b < cend; b++) if (p[b]) bits |= (1u << b);
                } else {
                    const float* p = (const float*)maskp + rbase + c0;
                    for (int b = 0; b < cend; b++) if (p[b] != 0.0f) bits |= (1u << b);
                }
            }
        }
        g_maskb[((size_t)bb * MROWS + row) * MW + w] = bits;
    } else {
        if (blockIdx.x >= LUTG) return;
        int wid = threadIdx.x >> 5, lane = threadIdx.x & 31;
        int cls = blockIdx.x * 8 + wid;
        if (cls >= NCLS) return;
        int d0 = cls % 13 - 6;
        int d1 = (cls / 13) % 13 - 6;
        int d2 = cls / 169 - 6;
        float x0 = copysignf(log2f(1.0f + fabsf((float)d0)) * (1.0f / 3.0f), (float)d0);
        float x1 = copysignf(log2f(1.0f + fabsf((float)d1)) * (1.0f / 3.0f), (float)d1);
        float x2 = copysignf(log2f(1.0f + fabsf((float)d2)) * (1.0f / 3.0f), (float)d2);
        float acc[8];
#pragma unroll
        for (int h = 0; h < 8; h++) acc[h] = 0.0f;
        for (int tt = lane; tt < HIDs; tt += 32) {
            float hv = fmaxf(fmaf(x0, W1[tt], fmaf(x1, W1[HIDs + tt],
                            fmaf(x2, W1[2 * HIDs + tt], b1[tt]))), 0.0f);
#pragma unroll
            for (int h = 0; h < 8; h++) acc[h] = fmaf(hv, W2[tt * 8 + h], acc[h]);
        }
#pragma unroll
        for (int h = 0; h < 8; h++) {
#pragma unroll
            for (int o = 16; o > 0; o >>= 1)
                acc[h] += __shfl_xor_sync(0xffffffffu, acc[h], o);
        }
        if (lane == 0) {
#pragma unroll
            for (int h = 0; h < 8; h++) {
                float z = acc[h] + b2[h];
                g_blut[cls * 8 + h] = 16.0f / (1.0f + fexp(-z));
            }
        }
    }
}

// ============================================================
// Shared fp16 GEMM body
// ============================================================
#define TGS 72
#define TGBUF 18432
#define TGSTAGE (2 * TGBUF)
#define TG_SMEM (3 * TGSTAGE)

__device__ __forceinline__ void tgemm_body(
    char* dsm,
    const __half* __restrict__ A, const __half* __restrict__ W,
    const float* __restrict__ bias, float* __restrict__ C, int remap,
    __half* __restrict__ Oh, int donorm)
{
    const int tid = threadIdx.x;
    const int wid = tid >> 5;
    const int lane = tid & 31;
    const int m0 = blockIdx.x * 128;
    const int n0 = blockIdx.y * 128;
    const int wm = wid & 1;
    const int wn = wid >> 1;
    const uint32_t smb = smem_u32(dsm);

    float c[4][4][4];
#pragma unroll
    for (int i = 0; i < 4; i++)
#pragma unroll
        for (int j = 0; j < 4; j++)
#pragma unroll
            for (int k = 0; k < 4; k++) c[i][j][k] = 0.0f;

    auto prefetch = [&](int i) {
        const int s = i % 3;
        const int k0 = i * 64;
        const uint32_t bA = smb + s * TGSTAGE;
        const uint32_t bB = bA + TGBUF;
#pragma unroll
        for (int j = 0; j < 4; j++) {
            int x = tid + j * 256;
            int r = x >> 3, cc = x & 7;
            uint32_t off = (uint32_t)(r * TGS + cc * 8) * 2;
            cp_async16(bA + off, A + (size_t)(m0 + r) * Es + k0 + cc * 8);
            cp_async16(bB + off, W + (size_t)(n0 + r) * Es + k0 + cc * 8);
        }
    };

    prefetch(0); cp_commit();
    prefetch(1); cp_commit();

    const int arow = (lane & 7) + ((lane >> 3) & 1) * 8;
    const int acolo = ((lane >> 4) & 1) * 8;
    const int brow = (lane & 7) + ((lane >> 4) & 1) * 8;
    const int bcolo = ((lane >> 3) & 1) * 8;

    for (int i = 0; i < 4; i++) {
        if (i < 3) cp_wait1(); else cp_wait0();
        __syncthreads();
        if (i < 2) { prefetch(i + 2); cp_commit(); }

        const uint32_t bA = smb + (i % 3) * TGSTAGE;
        const uint32_t bB = bA + TGBUF;
#pragma unroll
        for (int ks = 0; ks < 4; ks++) {
            const int k0 = ks * 16;
            uint32_t a[4][4], b[2][4];
#pragma unroll
            for (int mt = 0; mt < 4; mt++)
                ldsm_x4(a[mt][0], a[mt][1], a[mt][2], a[mt][3],
                        bA + (uint32_t)((wm * 64 + mt * 16 + arow) * TGS + k0 + acolo) * 2);
#pragma unroll
            for (int g = 0; g < 2; g++)
                ldsm_x4(b[g][0], b[g][1], b[g][2], b[g][3],
                        bB + (uint32_t)((wn * 32 + g * 16 + brow) * TGS + k0 + bcolo) * 2);
#pragma unroll
            for (int mt = 0; mt < 4; mt++)
#pragma unroll
                for (int nt = 0; nt < 4; nt++)
                    mma16816(c[mt][nt], a[mt], b[nt >> 1][(nt & 1) * 2],
                             b[nt >> 1][(nt & 1) * 2 + 1]);
        }
    }

    const int tq = lane >> 2;
    const int tr = lane & 3;
#pragma unroll
    for (int mt = 0; mt < 4; mt++) {
        const int m = m0 + wm * 64 + mt * 16 + tq;
        float v0x[4], v0y[4], v1x[4], v1y[4];
#pragma unroll
        for (int nt = 0; nt < 4; nt++) {
            const int n = n0 + wn * 32 + nt * 8 + tr * 2;
            float bx = 0.0f, by = 0.0f;
            if (bias) { float2 bv = *(const float2*)(bias + n); bx = bv.x; by = bv.y; }
            v0x[nt] = c[mt][nt][0] + bx; v0y[nt] = c[mt][nt][1] + by;
            v1x[nt] = c[mt][nt][2] + bx; v1y[nt] = c[mt][nt][3] + by;
        }
        if (donorm) {
            float ss0 = 0.0f, ss1 = 0.0f;
#pragma unroll
            for (int nt = 0; nt < 4; nt++) {
                ss0 = fmaf(v0x[nt], v0x[nt], fmaf(v0y[nt], v0y[nt], ss0));
                ss1 = fmaf(v1x[nt], v1x[nt], fmaf(v1y[nt], v1y[nt], ss1));
            }
            ss0 += __shfl_xor_sync(0xffffffffu, ss0, 1);
            ss0 += __shfl_xor_sync(0xffffffffu, ss0, 2);
            ss1 += __shfl_xor_sync(0xffffffffu, ss1, 1);
            ss1 += __shfl_xor_sync(0xffffffffu, ss1, 2);
            float i0 = 1.0f / fmaxf(sqrtf(ss0), 1e-12f);
            float i1 = 1.0f / fmaxf(sqrtf(ss1), 1e-12f);
#pragma unroll
            for (int nt = 0; nt < 4; nt++) {
                v0x[nt] *= i0; v0y[nt] *= i0;
                v1x[nt] *= i1; v1y[nt] *= i1;
            }
        }
#pragma unroll
        for (int nt = 0; nt < 4; nt++) {
            const int n = n0 + wn * 32 + nt * 8 + tr * 2;
            size_t a0, a1;
            if (remap) {
                const int hh = n >> 5, hd = n & 31;
                int bbw = m / Ls, l = m - bbw * Ls;
                a0 = ((size_t)(bbw * Hs + hh) * Ls + l) * HDs + hd;
                int m2 = m + 8;
                int bbw2 = m2 / Ls, l2 = m2 - bbw2 * Ls;
                a1 = ((size_t)(bbw2 * Hs + hh) * Ls + l2) * HDs + hd;
            } else {
                a0 = (size_t)m * Es + n;
                a1 = (size_t)(m + 8) * Es + n;
            }
            if (Oh) {
                *(uint32_t*)(Oh + a0) = packh(v0x[nt], v0y[nt]);
                *(uint32_t*)(Oh + a1) = packh(v1x[nt], v1y[nt]);
            } else {
                *(float2*)(C + a0) = make_float2(v0x[nt], v0y[nt]);
                *(float2*)(C + a1) = make_float2(v1x[nt], v1y[nt]);
            }
        }
    }
}

// Launch 2: Q/K/V projections (z=0..2) + bias gather (z=3)
__global__ __launch_bounds__(256, 2) void qkv_gemm_kernel(
    const float* __restrict__ bq, const float* __restrict__ bk,
    const float* __restrict__ indices)
{
    extern __shared__ char dsm[];
    const int z = blockIdx.z;
    if (z == 3) {
        int p = (blockIdx.y * gridDim.x + blockIdx.x) * 256 + threadIdx.x;
        if (p >= LLs) return;
        int i = p / Ls, j = p - i * Ls;
        int q0 = __float2int_rn(indices[p * 3 + 0]) + 6;
        int q1 = __float2int_rn(indices[p * 3 + 1]) + 6;
        int q2 = __float2int_rn(indices[p * 3 + 2]) + 6;
        int cls = q0 + 13 * q1 + 169 * q2;
        float4 v0 = *(const float4*)(g_blut + cls * 8);
        float4 v1 = *(const float4*)(g_blut + cls * 8 + 4);
        float vals[8] = { v0.x, v0.y, v0.z, v0.w, v1.x, v1.y, v1.z, v1.w };
#pragma unroll
        for (int h = 0; h < 8; h++)
            g_bias[(size_t)h * (MROWS * BSTR) + i * BSTR + j] = vals[h];
        return;
    }
    const __half* A  = (z == 0) ? g_xq : (z == 1) ? g_xk : g_xv;
    const __half* W  = g_w4 + (size_t)z * Es * Es;
    const float* bias = (z == 0) ? bq : (z == 1) ? bk : nullptr;
    __half* Oh = (z == 0) ? g_qh : (z == 1) ? g_kh : g_vh;
    tgemm_body(dsm, A, W, bias, nullptr, 1, Oh, z < 2);
}

// Launch 4: output projection -> fp32 d_out
__global__ __launch_bounds__(256, 2) void out_gemm_kernel(
    const float* __restrict__ bw, float* __restrict__ out)
{
    extern __shared__ char dsm[];
    tgemm_body(dsm, g_a, g_w4 + 3 * (size_t)Es * Es, bw, out, 0, nullptr, 0);
}

// ============================================================
// Launch 3: persistent fp16 attention per (head, window).
// 256 threads / 8 warps; 110.6 KB SMEM -> 2 CTAs/SM.
// ============================================================
#define ASTR 40
#define ABUF 30720
#define OFF_QH (0 * ABUF)
#define OFF_KH (1 * ABUF)
#define OFF_VH (2 * ABUF)
#define OFF_RMAX (3 * ABUF)
#define OFF_RSUM (OFF_RMAX + 512)
#define OFF_ORED (OFF_RSUM + 512)
#define ORSTR 34
#define ATT3_SMEM (OFF_ORED + 4 * 32 * ORSTR * 4)   // 110592

__global__ __launch_bounds__(256, 2) void attn3_kernel(const float* __restrict__ scalep)
{
    extern __shared__ char sm2[];
    float* redmax = (float*)(sm2 + OFF_RMAX);
    float* redsum = (float*)(sm2 + OFF_RSUM);
    float* ored   = (float*)(sm2 + OFF_ORED);
    const uint32_t smb = smem_u32(sm2);

    const int tid = threadIdx.x;
    const int wid = tid >> 5;
    const int lane = tid & 31;
    const int h = blockIdx.x;
    const int bb = blockIdx.y;
    const size_t gbase = (size_t)(bb * Hs + h) * (Ls * HDs);

    // ---- fill Q,K,V once ----
    {
        const __half* gsrc[3] = { g_qh + gbase, g_kh + gbase, g_vh + gbase };
#pragma unroll
        for (int arr = 0; arr < 3; arr++)
            for (int i = tid; i < 1372; i += 256) {
                int row = i >> 2, ch = i & 3;
                cp_async16(smb + arr * ABUF + row * 80 + ch * 16,
                           gsrc[arr] + row * HDs + ch * 8);
            }
        for (int i = tid; i < 492; i += 256) {
            int arr = i / 164, j = i - arr * 164;
            int r = 343 + (j >> 2), ch = j & 3;
            *(uint4*)(sm2 + arr * ABUF + r * 80 + ch * 16) = make_uint4(0, 0, 0, 0);
        }
        cp_commit();
        cp_wait0();
        __syncthreads();
    }

    const int wm = wid & 1;
    const int wn = wid >> 1;
    const int nbase = wn * 96;

    const int arow = (lane & 7) + ((lane >> 3) & 1) * 8;
    const int acolo = ((lane >> 4) & 1) * 8;
    const int brow = (lane & 7) + ((lane >> 4) & 1) * 8;
    const int bcolo = ((lane >> 3) & 1) * 8;

    const float invscale = 1.0f / fmaxf(scalep[0], 0.01f);
    const float* bias0 = g_bias + (size_t)h * (MROWS * BSTR);
    const uint32_t* mrowb = g_maskb + (size_t)bb * (MROWS * MW) + wn * 3;
    const int r0 = wm * 16 + (lane >> 2);
    const int r1 = r0 + 8;
    const int ncol = (lane & 3) * 2;
    const int lane16 = lane & 15;
    const int halfr = lane >> 4;

    for (int qt = 0; qt < 11; qt++) {
        const int q0 = qt * 32;
        const int qrow0 = q0 + r0, qrow1 = q0 + r1;

        const uint32_t* mp0 = mrowb + (size_t)qrow0 * MW;
        const uint32_t* mp1 = mrowb + (size_t)qrow1 * MW;
        uint32_t mw0[3] = { mp0[0], mp0[1], mp0[2] };
        uint32_t mw1[3] = { mp1[0], mp1[1], mp1[2] };
        const float* brow0 = bias0 + (size_t)qrow0 * BSTR + nbase + ncol;
        const float* brow1 = bias0 + (size_t)qrow1 * BSTR + nbase + ncol;

        uint32_t qh[2][4];
#pragma unroll
        for (int kk = 0; kk < 2; kk++) {
            uint32_t ro = (uint32_t)((q0 + wm * 16 + arow) * ASTR + kk * 16 + acolo) * 2;
            ldsm_x4(qh[kk][0], qh[kk][1], qh[kk][2], qh[kk][3], smb + OFF_QH + ro);
        }

        float c[12][4];
        float mx0 = -FLT_MAX, mx1 = -FLT_MAX;
#pragma unroll
        for (int g = 0; g < 6; g++) {
            float2 bT00 = *(const float2*)(brow0 + g * 16);
            float2 bT10 = *(const float2*)(brow0 + g * 16 + 8);
            float2 bT01 = *(const float2*)(brow1 + g * 16);
            float2 bT11 = *(const float2*)(brow1 + g * 16 + 8);

            uint32_t bh[2][4];
#pragma unroll
            for (int kk = 0; kk < 2; kk++) {
                uint32_t rb = (uint32_t)((nbase + g * 16 + brow) * ASTR + kk * 16 + bcolo) * 2;
                ldsm_x4(bh[kk][0], bh[kk][1], bh[kk][2], bh[kk][3], smb + OFF_KH + rb);
            }
            float cg[2][4];
#pragma unroll
            for (int nt = 0; nt < 2; nt++)
#pragma unroll
                for (int e = 0; e < 4; e++) cg[nt][e] = 0.0f;
#pragma unroll
            for (int kk = 0; kk < 2; kk++)
#pragma unroll
                for (int nt = 0; nt < 2; nt++)
                    mma16816(cg[nt], qh[kk], bh[kk][nt * 2], bh[kk][nt * 2 + 1]);
#pragma unroll
            for (int nt = 0; nt < 2; nt++) {
                const int t = g * 2 + nt;
                const int base = g * 16 + nt * 8;
                const int wI = base >> 5;
                uint32_t mb0 = (mw0[wI] >> ((base & 31) + ncol)) & 3u;
                uint32_t mb1 = (mw1[wI] >> ((base & 31) + ncol)) & 3u;
                float2 b0v = nt ? bT10 : bT00;
                float2 b1v = nt ? bT11 : bT01;
                c[t][0] = (mb0 & 1u) ? -100000.0f : fmaf(cg[nt][0], invscale, b0v.x);
                c[t][1] = (mb0 & 2u) ? -100000.0f : fmaf(cg[nt][1], invscale, b0v.y);
                c[t][2] = (mb1 & 1u) ? -100000.0f : fmaf(cg[nt][2], invscale, b1v.x);
                c[t][3] = (mb1 & 2u) ? -100000.0f : fmaf(cg[nt][3], invscale, b1v.y);
                mx0 = fmaxf(mx0, fmaxf(c[t][0], c[t][1]));
                mx1 = fmaxf(mx1, fmaxf(c[t][2], c[t][3]));
            }
        }

        mx0 = fmaxf(mx0, __shfl_xor_sync(0xffffffffu, mx0, 1));
        mx0 = fmaxf(mx0, __shfl_xor_sync(0xffffffffu, mx0, 2));
        mx1 = fmaxf(mx1, __shfl_xor_sync(0xffffffffu, mx1, 1));
        mx1 = fmaxf(mx1, __shfl_xor_sync(0xffffffffu, mx1, 2));

        float s0 = 0.0f, s1 = 0.0f;
#pragma unroll
        for (int t = 0; t < 12; t++) {
            float e0 = fexp(c[t][0] - mx0); c[t][0] = e0; s0 += e0;
            float e1 = fexp(c[t][1] - mx0); c[t][1] = e1; s0 += e1;
            float e2 = fexp(c[t][2] - mx1); c[t][2] = e2; s1 += e2;
            float e3 = fexp(c[t][3] - mx1); c[t][3] = e3; s1 += e3;
        }
        s0 += __shfl_xor_sync(0xffffffffu, s0, 1);
        s0 += __shfl_xor_sync(0xffffffffu, s0, 2);
        s1 += __shfl_xor_sync(0xffffffffu, s1, 1);
        s1 += __shfl_xor_sync(0xffffffffu, s1, 2);
        if ((lane & 3) == 0) {
            redmax[wn * 32 + r0] = mx0; redsum[wn * 32 + r0] = s0;
            redmax[wn * 32 + r1] = mx1; redsum[wn * 32 + r1] = s1;
        }
        __syncthreads();
        float f0, f1;
        {
            float gm0 = -FLT_MAX, gm1 = -FLT_MAX;
#pragma unroll
            for (int qd = 0; qd < 4; qd++) {
                gm0 = fmaxf(gm0, redmax[qd * 32 + r0]);
                gm1 = fmaxf(gm1, redmax[qd * 32 + r1]);
            }
            float S0 = 0.0f, S1 = 0.0f;
#pragma unroll
            for (int qd = 0; qd < 4; qd++) {
                S0 += redsum[qd * 32 + r0] * fexp(redmax[qd * 32 + r0] - gm0);
                S1 += redsum[qd * 32 + r1] * fexp(redmax[qd * 32 + r1] - gm1);
            }
            f0 = fexp(mx0 - gm0) / S0;
            f1 = fexp(mx1 - gm1) / S1;
        }

        float oc[4][4];
#pragma unroll
        for (int nt = 0; nt < 4; nt++)
#pragma unroll
            for (int e = 0; e < 4; e++) oc[nt][e] = 0.0f;

#pragma unroll
        for (int kt = 0; kt < 6; kt++) {
            uint32_t ph[4];
#pragma unroll
            for (int half = 0; half < 2; half++) {
                const float* cc = c[2 * kt + half];
                ph[half * 2 + 0] = packh(cc[0], cc[1]);
                ph[half * 2 + 1] = packh(cc[2], cc[3]);
            }
            const int krow = nbase + kt * 16;
            uint32_t vh[2][4];
#pragma unroll
            for (int g = 0; g < 2; g++) {
                uint32_t ad = (uint32_t)((krow + arow) * ASTR + g * 16 + acolo) * 2;
                ldsm_x4_t(vh[g][0], vh[g][1], vh[g][2], vh[g][3], smb + OFF_VH + ad);
            }
#pragma unroll
            for (int nt = 0; nt < 4; nt++) {
                const int g = nt >> 1, i2 = (nt & 1) * 2;
                mma16816(oc[nt], ph, vh[g][i2], vh[g][i2 + 1]);
            }
        }
#pragma unroll
        for (int nt = 0; nt < 4; nt++) {
            oc[nt][0] *= f0; oc[nt][1] *= f0;
            oc[nt][2] *= f1; oc[nt][3] *= f1;
        }

        {
            float* dst = ored + (size_t)wn * (32 * ORSTR);
#pragma unroll
            for (int nt = 0; nt < 4; nt++) {
                *(float2*)(dst + r0 * ORSTR + nt * 8 + ncol) = make_float2(oc[nt][0], oc[nt][1]);
                *(float2*)(dst + r1 * ORSTR + nt * 8 + ncol) = make_float2(oc[nt][2], oc[nt][3]);
            }
        }
        __syncthreads();
#pragma unroll
        for (int p = 0; p < 2; p++) {
            int row = wid * 4 + p * 2 + halfr;
            int qrow = q0 + row;
            if (qrow < Ls) {
                int col = lane16 * 2;
                float s0o = 0.0f, s1o = 0.0f;
#pragma unroll
                for (int qd = 0; qd < 4; qd++) {
                    float2 v = *(float2*)(ored + qd * (32 * ORSTR) + row * ORSTR + col);
                    s0o += v.x; s1o += v.y;
                }
                size_t ad = (size_t)(bb * Ls + qrow) * Es + h * HDs + col;
                *(uint32_t*)(g_a + ad) = packh(s0o, s1o);
            }
        }
        __syncthreads();
    }
}

// ============================================================
// launch
// ============================================================
extern "C" void kernel_launch(void* const* d_in, const int* in_sizes, int n_in,
                              void* d_out, int out_size)
{
    (void)in_sizes; (void)n_in; (void)out_size;
    const float* query   = (const float*)d_in[0];
    const float* key     = (const float*)d_in[1];
    const float* value   = (const float*)d_in[2];
    const float* indices = (const float*)d_in[3];
    const void*  mask    = d_in[4];
    const float* Wq      = (const float*)d_in[5];
    const float* bq      = (const float*)d_in[6];
    const float* Wk      = (const float*)d_in[7];
    const float* bk      = (const float*)d_in[8];
    const float* Wv      = (const float*)d_in[9];
    const float* Ww      = (const float*)d_in[10];
    const float* bw      = (const float*)d_in[11];
    const float* scale   = (const float*)d_in[12];
    const float* W1      = (const float*)d_in[13];
    const float* b1      = (const float*)d_in[14];
    const float* W2      = (const float*)d_in[15];
    const float* b2      = (const float*)d_in[16];
    float* out = (float*)d_out;

    cudaFuncSetAttribute(qkv_gemm_kernel, cudaFuncAttributeMaxDynamicSharedMemorySize,
                         TG_SMEM);
    cudaFuncSetAttribute(out_gemm_kernel, cudaFuncAttributeMaxDynamicSharedMemorySize,
                         TG_SMEM);
    cudaFuncSetAttribute(attn3_kernel, cudaFuncAttributeMaxDynamicSharedMemorySize,
                         ATT3_SMEM);

    const int n4 = ROWSs * Es / 4;
    const int splitg = (n4 + 255) / 256;

    // L1: input rounding + weights + mask bit-pack + CPB LUT (all independent)
    prep_kernel<<<dim3(splitg, 6), 256>>>((const float4*)query, (const float4*)key,
                                          (const float4*)value, n4, Wq, Wk, Wv, Ww,
                                          mask, W1, b1, W2, b2);
    // L2: Q/K/V projections + bias gather
    qkv_gemm_kernel<<<dim3(ROWSs / 128, Es / 128, 4), 256, TG_SMEM>>>(bq, bk, indices);
    // L3: attention
    attn3_kernel<<<dim3(Hs, BBs), 256, ATT3_SMEM>>>(scale);
    // L4: output projection
    out_gemm_kernel<<<dim3(ROWSs / 128, Es / 128), 256, TG_SMEM>>>(bw, out);
}